// round 3
// baseline (speedup 1.0000x reference)
#include <cuda_runtime.h>
#include <cuda_bf16.h>
#include <cstdint>

// Problem shape (BGEM3 sparse-embedding head)
#define BB 32
#define SS 1024
#define HH 1024
#define VV 250002

#define ROWS      (BB * SS)          // 32768
#define OUT_F4    ((BB * VV) / 4)    // 2000016 float4

#define CBLOCKS   4096               // compute blocks: 8 warps * 1 row/warp
#define ZBLOCKS   1024               // zero blocks
#define NBLOCKS   (CBLOCKS + ZBLOCKS)
#define ZTHREADS  (ZBLOCKS * 256)
#define ZITERS    8                  // ceil(OUT_F4 / ZTHREADS)

#define TAIL_BLOCKS 32               // last arrivals do the scatter
#define ROWS_PER_TAIL (ROWS / TAIL_BLOCKS)   // 1024
#define ROWS_PER_THREAD (ROWS_PER_TAIL / 256) // 4

// Scratch for per-row token weights (fully written every call; deterministic).
__device__ float g_tw[ROWS];
// Epilogue coordination. Start 0, reset to 0 by the last finisher each call.
__device__ int g_arrive = 0;
__device__ int g_done   = 0;

__global__ __launch_bounds__(256) void bgem3_fused(
    const float4* __restrict__ hidden,   // [B*S, H/4]
    const int*    __restrict__ ids,      // [B*S]
    const float4* __restrict__ W4,       // [H/4]
    const float*  __restrict__ bias,     // [1]
    float4*       __restrict__ out4)     // [B*V/4]
{
    const int bid = blockIdx.x;
    const int tid = threadIdx.x;
    float*    out = (float*)out4;

    if ((bid % 5) == 4) {
        // ---- zero role: write 32 KB of zeros ----
        const int zb = bid / 5;
        const float4 z = make_float4(0.f, 0.f, 0.f, 0.f);
        int idx = zb * 256 + tid;
#pragma unroll
        for (int i = 0; i < ZITERS; i++) {
            if (idx < OUT_F4) out4[idx] = z;
            idx += ZTHREADS;
        }
    } else {
        // ---- compute role: one warp per hidden row ----
        const int cid = (bid / 5) * 4 + (bid % 5);

        __shared__ float4 w[HH / 4];  // 4 KB
        w[tid] = W4[tid];
        __syncthreads();

        const int warp = tid >> 5;
        const int lane = tid & 31;
        const int row  = cid * 8 + warp;

        const float4* h = hidden + (size_t)row * (HH / 4);

        float sum = 0.0f;
#pragma unroll
        for (int i = 0; i < 8; i++) {
            const int idx = lane + i * 32;
            const float4 hv = h[idx];
            const float4 wv = w[idx];
            sum += hv.x * wv.x + hv.y * wv.y + hv.z * wv.z + hv.w * wv.w;
        }
#pragma unroll
        for (int off = 16; off > 0; off >>= 1)
            sum += __shfl_xor_sync(0xFFFFFFFFu, sum, off);

        if (lane == 0)
            g_tw[row] = fmaxf(sum + bias[0], 0.0f);   // ReLU
    }

    // ---- epilogue: last TAIL_BLOCKS arrivals scatter into the zeroed table ----
    __threadfence();          // make this block's stores visible GPU-wide
    __syncthreads();

    __shared__ int s_ticket;
    if (tid == 0) s_ticket = atomicAdd(&g_arrive, 1);
    __syncthreads();
    const int ticket = s_ticket;

    if (ticket < NBLOCKS - TAIL_BLOCKS) return;

    // Wait for every block's work (zeros + g_tw) to be complete.
    if (tid == 0) {
        while (atomicAdd(&g_arrive, 0) < NBLOCKS) { }
    }
    __syncthreads();
    __threadfence();

    const int slice = ticket - (NBLOCKS - TAIL_BLOCKS);   // 0..31
    int row = slice * ROWS_PER_TAIL + tid;
#pragma unroll
    for (int i = 0; i < ROWS_PER_THREAD; i++) {
        const float tw = g_tw[row];
        if (tw > 0.0f) {
            const int token = ids[row];
            // tokens 0..3 masked to zero in the reference; table is zeroed,
            // so skipping them is equivalent.
            if (token >= 4) {
                const int b = row >> 10;   // row / SS
                // post-ReLU weights >= 0, table init 0 -> IEEE-754 bits are
                // monotone as signed int: int atomicMax == exact float max.
                atomicMax(reinterpret_cast<int*>(out + (size_t)b * VV + token),
                          __float_as_int(tw));
            }
        }
        row += 256;
    }

    // Completion count; last scatter block resets counters for next replay.
    __syncthreads();
    if (tid == 0) {
        const int u = atomicAdd(&g_done, 1);
        if (u == TAIL_BLOCKS - 1) {
            g_done   = 0;
            g_arrive = 0;
            __threadfence();
        }
    }
}

extern "C" void kernel_launch(void* const* d_in, const int* in_sizes, int n_in,
                              void* d_out, int out_size)
{
    const float4* hidden = (const float4*)d_in[0];  // [B,S,H] f32
    const int*    ids    = (const int*)d_in[1];     // [B,S] i32
    const float4* W4     = (const float4*)d_in[2];  // [1,H] f32
    const float*  bias   = (const float*)d_in[3];   // [1] f32

    bgem3_fused<<<NBLOCKS, 256>>>(hidden, ids, W4, bias, (float4*)d_out);
}

// round 4
// speedup vs baseline: 1.0266x; 1.0266x over previous
#include <cuda_runtime.h>
#include <cuda_bf16.h>
#include <cstdint>

// Problem shape (BGEM3 sparse-embedding head)
#define BB 32
#define SS 1024
#define HH 1024
#define VV 250002

#define ROWS      (BB * SS)          // 32768
#define OUT_F4    ((BB * VV) / 4)    // 2000016 float4

#define ZBLOCKS   512                // zero blocks (bid 0..511) -- all in wave 1
#define CBLOCKS   4096               // compute blocks: 8 warps * 1 row/warp
#define NBLOCKS   (ZBLOCKS + CBLOCKS)
#define ZTHREADS  (ZBLOCKS * 256)    // 131072
#define ZITERS    16                 // ceil(OUT_F4 / ZTHREADS) = 15.26 -> 16

// Epilogue coordination. Start 0; last compute block resets both -> each
// graph replay sees identical initial state (deterministic).
__device__ int g_zero_done = 0;      // counts completed zero blocks
__device__ int g_cdone     = 0;      // counts completed compute blocks

__global__ __launch_bounds__(256) void bgem3_fused(
    const float4* __restrict__ hidden,   // [B*S, H/4]
    const int*    __restrict__ ids,      // [B*S]
    const float4* __restrict__ W4,       // [H/4]
    const float*  __restrict__ bias,     // [1]
    float4*       __restrict__ out4)     // [B*V/4]
{
    const int bid = blockIdx.x;
    const int tid = threadIdx.x;
    float*    out = (float*)out4;

    if (bid < ZBLOCKS) {
        // ---- zero role: 512 blocks, 64 KB each, issued in wave 1 ----
        const float4 z = make_float4(0.f, 0.f, 0.f, 0.f);
        int idx = bid * 256 + tid;
#pragma unroll
        for (int i = 0; i < ZITERS; i++) {
            if (idx < OUT_F4) out4[idx] = z;
            idx += ZTHREADS;
        }
        __threadfence();                    // make zeros visible GPU-wide
        __syncthreads();
        if (tid == 0) atomicAdd(&g_zero_done, 1);
        return;
    }

    // ---- compute role: one warp per hidden row ----
    const int cid = bid - ZBLOCKS;          // 0..CBLOCKS-1

    __shared__ float4 w[HH / 4];            // 4 KB
    w[tid] = W4[tid];
    __syncthreads();

    const int warp = tid >> 5;
    const int lane = tid & 31;
    const int row  = cid * 8 + warp;        // [0, ROWS)

    const float4* h = hidden + (size_t)row * (HH / 4);

    float sum = 0.0f;
#pragma unroll
    for (int i = 0; i < 8; i++) {
        const int idx = lane + i * 32;
        const float4 hv = h[idx];
        const float4 wv = w[idx];
        sum += hv.x * wv.x + hv.y * wv.y + hv.z * wv.z + hv.w * wv.w;
    }
#pragma unroll
    for (int off = 16; off > 0; off >>= 1)
        sum += __shfl_xor_sync(0xFFFFFFFFu, sum, off);

    if (lane == 0) {
        const float tw = sum + bias[0];
        if (tw > 0.0f) {
            const int token = ids[row];     // load before the spin (overlap)
            // tokens 0..3 are masked to zero in the reference; table is
            // zeroed, so skipping them is equivalent.
            if (token >= 4) {
                // Wait until all zero blocks have committed their stores.
                // Zero blocks are bids 0..511 (scheduled first, wave 1),
                // so this cannot deadlock.
                volatile int* zd = &g_zero_done;
                while (*zd < ZBLOCKS) { __nanosleep(200); }

                const int b = row >> 10;    // row / SS
                // post-ReLU weights >= 0 and table init is 0 -> IEEE-754
                // bits are monotone as signed int: int atomicMax == exact
                // float max.
                atomicMax(reinterpret_cast<int*>(out + (size_t)b * VV + token),
                          __float_as_int(tw));
            }
        }
    }

    // Counter reset for the next graph replay: the LAST compute block (all
    // spins already passed by then) resets both counters.
    __syncthreads();
    if (tid == 0) {
        const int t = atomicAdd(&g_cdone, 1);
        if (t == CBLOCKS - 1) {
            g_cdone     = 0;
            g_zero_done = 0;
            __threadfence();
        }
    }
}

extern "C" void kernel_launch(void* const* d_in, const int* in_sizes, int n_in,
                              void* d_out, int out_size)
{
    const float4* hidden = (const float4*)d_in[0];  // [B,S,H] f32
    const int*    ids    = (const int*)d_in[1];     // [B,S] i32
    const float4* W4     = (const float4*)d_in[2];  // [1,H] f32
    const float*  bias   = (const float*)d_in[3];   // [1] f32

    bgem3_fused<<<NBLOCKS, 256>>>(hidden, ids, W4, bias, (float4*)d_out);
}

// round 5
// speedup vs baseline: 1.2237x; 1.1920x over previous
#include <cuda_runtime.h>
#include <cuda_bf16.h>
#include <cstdint>

// Problem shape (BGEM3 sparse-embedding head)
#define BB 32
#define SS 1024
#define HH 1024
#define VV 250002

#define ROWS      (BB * SS)          // 32768
#define OUT_F4    ((BB * VV) / 4)    // 2000016 float4

#define CBLOCKS   4096               // compute blocks: 8 warps * 1 row/warp
#define ZBLOCKS   1024               // zero blocks
#define NBLOCKS   (CBLOCKS + ZBLOCKS)
#define ZTHREADS  (ZBLOCKS * 256)
#define ZITERS    8                  // ceil(OUT_F4 / ZTHREADS)

// Scratch for per-row token weights (fully written every call; deterministic).
__device__ float g_tw[ROWS];

// Fused kernel (R2 structure, unchanged — it ran at the memory roof):
// 4/5 blocks compute dot products -> g_tw, 1/5 blocks zero the output table.
__global__ __launch_bounds__(256) void bgem3_fused(
    const float4* __restrict__ hidden,   // [B*S, H/4]
    const float4* __restrict__ W4,       // [H/4]
    const float*  __restrict__ bias,     // [1]
    float4*       __restrict__ out4)     // [B*V/4]
{
    const int bid = blockIdx.x;
    const int tid = threadIdx.x;

    if ((bid % 5) == 4) {
        // ---- zero role ----
        const int zb = bid / 5;
        const float4 z = make_float4(0.f, 0.f, 0.f, 0.f);
        int idx = zb * 256 + tid;
#pragma unroll
        for (int i = 0; i < ZITERS; i++) {
            if (idx < OUT_F4) out4[idx] = z;
            idx += ZTHREADS;
        }
        return;
    }

    // ---- compute role ----
    const int cid = (bid / 5) * 4 + (bid % 5);

    __shared__ float4 w[HH / 4];  // 4 KB
    w[tid] = W4[tid];
    __syncthreads();

    const int warp = tid >> 5;
    const int lane = tid & 31;
    const int row  = cid * 8 + warp;

    const float4* h = hidden + (size_t)row * (HH / 4);

    float sum = 0.0f;
#pragma unroll
    for (int i = 0; i < 8; i++) {
        const int idx = lane + i * 32;
        const float4 hv = h[idx];
        const float4 wv = w[idx];
        sum += hv.x * wv.x + hv.y * wv.y + hv.z * wv.z + hv.w * wv.w;
    }
#pragma unroll
    for (int off = 16; off > 0; off >>= 1)
        sum += __shfl_xor_sync(0xFFFFFFFFu, sum, off);

    if (lane == 0)
        g_tw[row] = fmaxf(sum + bias[0], 0.0f);   // ReLU
}

// Scatter kernel: latency-optimized.
//  - both loads issued unconditionally up front (MLP=2, no dependent branch)
//  - red.global.max.s32: no-return reduction (no result scoreboard)
//  - 256 blocks x 128 threads: 2 blocks/SM, short tail
__global__ __launch_bounds__(128) void bgem3_scatter(
    const int* __restrict__ ids,   // [B*S]
    float*     __restrict__ out)   // [B, V], zeroed by bgem3_fused
{
    const int row = blockIdx.x * 128 + threadIdx.x;   // [0, ROWS)

    // Issue both loads immediately; they are independent.
    const float tw    = g_tw[row];
    const int   token = __ldg(ids + row);

    // tokens 0..3 masked to zero in the reference; table is zeroed, so
    // skipping them is equivalent.
    if (tw > 0.0f && token >= 4) {
        const int b = row >> 10;   // row / SS
        // post-ReLU weights >= 0, table init 0 -> IEEE-754 bits monotone as
        // signed int: integer max == exact float max.
        int* addr = reinterpret_cast<int*>(out + (size_t)b * VV + token);
        const int v = __float_as_int(tw);
        asm volatile("red.global.max.s32 [%0], %1;" :: "l"(addr), "r"(v)
                     : "memory");
    }
}

extern "C" void kernel_launch(void* const* d_in, const int* in_sizes, int n_in,
                              void* d_out, int out_size)
{
    const float4* hidden = (const float4*)d_in[0];  // [B,S,H] f32
    const int*    ids    = (const int*)d_in[1];     // [B,S] i32
    const float4* W4     = (const float4*)d_in[2];  // [1,H] f32
    const float*  bias   = (const float*)d_in[3];   // [1] f32
    float*        out    = (float*)d_out;           // [B,V] f32

    bgem3_fused<<<NBLOCKS, 256>>>(hidden, W4, bias, (float4*)d_out);
    bgem3_scatter<<<ROWS / 128, 128>>>(ids, out);
}